// round 9
// baseline (speedup 1.0000x reference)
#include <cuda_runtime.h>
#include <cuda_fp16.h>
#include <stdint.h>

// ============================================================================
// Int8Linear — harness dtypes: x fp16->float32, w int8->int32, out fp16->float32.
//   out[m,n] = f32( fp16( fp32acc( x[m,:] . w[n,:] ) * scale[n] ) )
// M=8192, N=11008, K=4096.
// Round 9: ring-pipelined fragments (a-ring across substeps, b-ring across
// mma groups) at LOWER reg pressure than round 7; grid swizzle kept.
// CTA tile 128x256, warp tile 64x64, cp.async.cg 4-stage pipeline, SW128.
// ============================================================================

namespace {

constexpr int GM = 8192;
constexpr int GN = 11008;
constexpr int GK = 4096;
constexpr int BM = 128;
constexpr int BN = 256;
constexpr int BK = 64;                    // 64 fp16 = 128B row (SW128 atom)
constexpr int KIT = GK / BK;              // 64
constexpr int NT = GN / BN;               // 43
constexpr int MT = GM / BM;               // 64
constexpr int STAGES = 4;
constexpr int TILE_A  = BM * 128;         // 16 KB
constexpr int TILE_W  = BN * 128;         // 32 KB
constexpr int STAGE_B = TILE_A + TILE_W;  // 48 KB
constexpr int SMEM_BYTES = 1024 + STAGES * STAGE_B;  // 197632 B
constexpr int GRP = 8;                    // n-tiles per rasterization group

__device__ __align__(1024) __half g_xh[(size_t)GM * GK];   // 64 MB
__device__ __align__(1024) __half g_wh[(size_t)GN * GK];   // 90 MB

#define SW128(o) ((o) ^ (((o) >> 3) & 0x70u))

__device__ __forceinline__ uint32_t smem_u32(const void* p) {
    uint32_t a;
    asm("{ .reg .u64 t; cvta.to.shared.u64 t, %1; cvt.u32.u64 %0, t; }"
        : "=r"(a) : "l"(p));
    return a;
}

// exact packed-int8x4 -> 2x half2: ((b^0x80)|0x6400) - 1152
__device__ __forceinline__ void cvt4_i8_f16(uint32_t v, uint32_t* h2) {
    const uint32_t u = v ^ 0x80808080u;
    uint32_t lo = __byte_perm(u, 0x64646464u, 0x4140);
    uint32_t hi = __byte_perm(u, 0x64646464u, 0x4342);
    const uint32_t bias_u = 0x64806480u;  // half2(1152, 1152)
    __half2 a = __hsub2(*reinterpret_cast<const __half2*>(&lo),
                        *reinterpret_cast<const __half2*>(&bias_u));
    __half2 c = __hsub2(*reinterpret_cast<const __half2*>(&hi),
                        *reinterpret_cast<const __half2*>(&bias_u));
    h2[0] = *reinterpret_cast<uint32_t*>(&a);
    h2[1] = *reinterpret_cast<uint32_t*>(&c);
}

// ---------------------------------------------------------------------------
__global__ void __launch_bounds__(256) prep_x(const float* __restrict__ x) {
    const size_t e = ((size_t)blockIdx.x * 256 + threadIdx.x) * 8;
    float4 f0 = *reinterpret_cast<const float4*>(x + e);
    float4 f1 = *reinterpret_cast<const float4*>(x + e + 4);
    __half2 h0 = __floats2half2_rn(f0.x, f0.y);
    __half2 h1 = __floats2half2_rn(f0.z, f0.w);
    __half2 h2 = __floats2half2_rn(f1.x, f1.y);
    __half2 h3 = __floats2half2_rn(f1.z, f1.w);
    uint4 st;
    st.x = *reinterpret_cast<uint32_t*>(&h0);
    st.y = *reinterpret_cast<uint32_t*>(&h1);
    st.z = *reinterpret_cast<uint32_t*>(&h2);
    st.w = *reinterpret_cast<uint32_t*>(&h3);
    *reinterpret_cast<uint4*>(g_xh + e) = st;
}

__global__ void __launch_bounds__(256) prep_w(const int* __restrict__ w) {
    const size_t e = ((size_t)blockIdx.x * 256 + threadIdx.x) * 8;
    int4 w0 = *reinterpret_cast<const int4*>(w + e);
    int4 w1 = *reinterpret_cast<const int4*>(w + e + 4);
    uint32_t t0 = __byte_perm((uint32_t)w0.x, (uint32_t)w0.y, 0x0040);
    uint32_t u0 = __byte_perm((uint32_t)w0.z, (uint32_t)w0.w, 0x0040);
    uint32_t r0 = __byte_perm(t0, u0, 0x5410);
    uint32_t t1 = __byte_perm((uint32_t)w1.x, (uint32_t)w1.y, 0x0040);
    uint32_t u1 = __byte_perm((uint32_t)w1.z, (uint32_t)w1.w, 0x0040);
    uint32_t r1 = __byte_perm(t1, u1, 0x5410);
    uint32_t h[4];
    cvt4_i8_f16(r0, h + 0);
    cvt4_i8_f16(r1, h + 2);
    *reinterpret_cast<uint4*>(g_wh + e) = make_uint4(h[0], h[1], h[2], h[3]);
}

// ---------------------------------------------------------------------------
__device__ __forceinline__ void cpa16(uint32_t dst, const void* src) {
    asm volatile("cp.async.cg.shared.global [%0], [%1], 16;"
                 :: "r"(dst), "l"(src) : "memory");
}
__device__ __forceinline__ void cp_commit() {
    asm volatile("cp.async.commit_group;" ::: "memory");
}
template <int N>
__device__ __forceinline__ void cp_wait() {
    asm volatile("cp.async.wait_group %0;" :: "n"(N) : "memory");
}
__device__ __forceinline__ void ldsm4(uint32_t* r, uint32_t addr) {
    asm volatile("ldmatrix.sync.aligned.m8n8.x4.shared.b16 {%0,%1,%2,%3}, [%4];"
                 : "=r"(r[0]), "=r"(r[1]), "=r"(r[2]), "=r"(r[3]) : "r"(addr));
}
__device__ __forceinline__ void mma16816(float* c, const uint32_t* a,
                                         uint32_t b0, uint32_t b1) {
    asm volatile(
        "mma.sync.aligned.m16n8k16.row.col.f32.f16.f16.f32 "
        "{%0,%1,%2,%3}, {%4,%5,%6,%7}, {%8,%9}, {%0,%1,%2,%3};"
        : "+f"(c[0]), "+f"(c[1]), "+f"(c[2]), "+f"(c[3])
        : "r"(a[0]), "r"(a[1]), "r"(a[2]), "r"(a[3]), "r"(b0), "r"(b1));
}

__global__ void __launch_bounds__(256, 1)
gemm_kernel(const float* __restrict__ scale, float* __restrict__ out) {
    extern __shared__ char smem[];
    const uint32_t raw   = smem_u32(smem);
    const uint32_t tiles = (raw + 1023u) & ~1023u;   // 1KB align for SW128

    const int tid  = threadIdx.x;
    const int lane = tid & 31;
    const int warp = tid >> 5;
    const int wm   = warp >> 2;   // 0..1  (64 m-rows each)
    const int wn   = warp & 3;    // 0..3  (64 n-cols each)

    // ---- grid swizzle: groups of GRP n-tiles x MT m-tiles ----
    const int lin    = blockIdx.x;            // 0 .. NT*MT-1
    const int grp    = lin / (GRP * MT);
    const int startn = grp * GRP;
    const int width  = (NT - startn < GRP) ? (NT - startn) : GRP;
    const int rem    = lin - grp * GRP * MT;
    const int n0     = (startn + rem % width) * BN;
    const int m0     = (rem / width) * BM;

    const __half* ag = g_xh + (size_t)m0 * GK;
    const __half* bg = g_wh + (size_t)n0 * GK;

    auto issue = [&](int kn) {
        const int s  = kn & (STAGES - 1);
        const int k0 = kn * BK;
        const uint32_t ab = tiles + s * STAGE_B;
        const uint32_t bb = ab + TILE_A;
#pragma unroll
        for (int p = 0; p < 4; ++p) {
            const int u = tid + p * 256;
            const int row = u >> 3, c = u & 7;
            const uint32_t o = SW128((uint32_t)(row * 128 + c * 16));
            cpa16(ab + o, ag + (size_t)row * GK + k0 + c * 8);
        }
#pragma unroll
        for (int p = 0; p < 8; ++p) {
            const int u = tid + p * 256;
            const int row = u >> 3, c = u & 7;
            const uint32_t o = SW128((uint32_t)(row * 128 + c * 16));
            cpa16(bb + o, bg + (size_t)row * GK + k0 + c * 8);
        }
        cp_commit();
    };

    issue(0); issue(1); issue(2);

    float acc[4][8][4];
#pragma unroll
    for (int t = 0; t < 4; ++t)
#pragma unroll
        for (int j = 0; j < 8; ++j)
#pragma unroll
            for (int e = 0; e < 4; ++e) acc[t][j][e] = 0.f;

    // ldmatrix per-lane address components (halves)
    const int row_a = wm * 64 + (lane & 15);                      // + t*16
    const int ka    = (lane >> 4) << 3;
    const int row_b = wn * 64 + ((lane >> 4) << 3) + (lane & 7);  // + g*16
    const int kb    = ((lane >> 3) & 1) << 3;

    for (int it = 0; it < KIT; ++it) {
        const int s = it & (STAGES - 1);

        cp_wait<2>();          // stage `it` complete (in-order groups)
        __syncthreads();       // visible CTA-wide; stage (it-1)&3 fully read

        if (it + 3 < KIT) issue(it + 3);
        else              cp_commit();   // keep group count invariant

        const uint32_t abase = tiles + s * STAGE_B;
        const uint32_t bbase = abase + TILE_A;

        // rings: a double-buffered across substeps, b across mma groups
        uint32_t a[2][4][4], b[2][4];

        auto lda = [&](int buf, int st) {
            const int k2 = st * 16;
#pragma unroll
            for (int t = 0; t < 4; ++t) {
                const uint32_t o = (uint32_t)((row_a + t * 16) * 128 + (k2 + ka) * 2);
                ldsm4(a[buf][t], abase + SW128(o));
            }
        };
        auto ldb = [&](int slot, int st, int g) {
            const uint32_t o = (uint32_t)((row_b + g * 16) * 128 + (st * 16 + kb) * 2);
            ldsm4(b[slot], bbase + SW128(o));
        };

        lda(0, 0);
        ldb(0, 0, 0);
#pragma unroll
        for (int st = 0; st < 4; ++st) {
            const int cur = st & 1;
#pragma unroll
            for (int g = 0; g < 4; ++g) {
                const int bs = g & 1;
                // prefetch under the 8 MMAs below
                if (g < 3)       ldb(bs ^ 1, st, g + 1);
                else if (st < 3) { lda(cur ^ 1, st + 1); ldb(bs ^ 1, st + 1, 0); }
#pragma unroll
                for (int t = 0; t < 4; ++t) {
                    mma16816(acc[t][2 * g],     a[cur][t], b[bs][0], b[bs][1]);
                    mma16816(acc[t][2 * g + 1], a[cur][t], b[bs][2], b[bs][3]);
                }
            }
        }
        // no trailing barrier: next iteration's wait+barrier orders reuse
    }

    // ---- epilogue: scale, fp16 round (match reference), fp32 store ----
    const int mrow = m0 + wm * 64 + (lane >> 2);
    const int ncol = n0 + wn * 64 + (lane & 3) * 2;
    float* og = out + (size_t)mrow * GN + ncol;
    const float* scp = scale + ncol;

#pragma unroll
    for (int t = 0; t < 4; ++t) {
#pragma unroll
        for (int j = 0; j < 8; ++j) {
            const float2 sc = *reinterpret_cast<const float2*>(scp + j * 8);
            float2 r0, r1;
            r0.x = __half2float(__float2half_rn(acc[t][j][0] * sc.x));
            r0.y = __half2float(__float2half_rn(acc[t][j][1] * sc.y));
            r1.x = __half2float(__float2half_rn(acc[t][j][2] * sc.x));
            r1.y = __half2float(__float2half_rn(acc[t][j][3] * sc.y));
            *reinterpret_cast<float2*>(og + (size_t)(t * 16) * GN + j * 8)     = r0;
            *reinterpret_cast<float2*>(og + (size_t)(t * 16 + 8) * GN + j * 8) = r1;
        }
    }
}

}  // namespace

extern "C" void kernel_launch(void* const* d_in, const int* in_sizes, int n_in,
                              void* d_out, int out_size) {
    const float* x     = (const float*)d_in[0];
    const int*   w     = (const int*)d_in[1];
    const float* scale = (const float*)d_in[2];
    float*       out   = (float*)d_out;

    cudaFuncSetAttribute(gemm_kernel,
                         cudaFuncAttributeMaxDynamicSharedMemorySize, SMEM_BYTES);

    prep_x<<<GM * GK / 8 / 256, 256>>>(x);   // 16384 blocks
    prep_w<<<GN * GK / 8 / 256, 256>>>(w);   // 22016 blocks
    gemm_kernel<<<NT * MT, 256, SMEM_BYTES>>>(scale, out);
}

// round 10
// speedup vs baseline: 1.5310x; 1.5310x over previous
#include <cuda_runtime.h>
#include <cuda_fp16.h>
#include <stdint.h>

// ============================================================================
// Int8Linear — harness dtypes: x fp16->float32, w int8->int32, out fp16->float32.
//   out[m,n] = f32( fp16( fp32acc( x[m,:] . w[n,:] ) * scale[n] ) )
// M=8192, N=11008, K=4096.
// Round 10: round-7 structure (best: 1773us) + grid swizzle ONLY.
// CTA tile 128x256, warp tile 64x64, cp.async.cg 4-stage pipeline, SW128,
// flat ldsm->mma blocks (ptxas schedules), fused scale epilogue.
// ============================================================================

namespace {

constexpr int GM = 8192;
constexpr int GN = 11008;
constexpr int GK = 4096;
constexpr int BM = 128;
constexpr int BN = 256;
constexpr int BK = 64;                    // 64 fp16 = 128B row (SW128 atom)
constexpr int KIT = GK / BK;              // 64
constexpr int NT = GN / BN;               // 43
constexpr int MT = GM / BM;               // 64
constexpr int STAGES = 4;
constexpr int TILE_A  = BM * 128;         // 16 KB
constexpr int TILE_W  = BN * 128;         // 32 KB
constexpr int STAGE_B = TILE_A + TILE_W;  // 48 KB
constexpr int SMEM_BYTES = 1024 + STAGES * STAGE_B;  // 197632 B
constexpr int GRP = 8;                    // n-tiles per rasterization group

__device__ __align__(1024) __half g_xh[(size_t)GM * GK];   // 64 MB
__device__ __align__(1024) __half g_wh[(size_t)GN * GK];   // 90 MB

#define SW128(o) ((o) ^ (((o) >> 3) & 0x70u))

__device__ __forceinline__ uint32_t smem_u32(const void* p) {
    uint32_t a;
    asm("{ .reg .u64 t; cvta.to.shared.u64 t, %1; cvt.u32.u64 %0, t; }"
        : "=r"(a) : "l"(p));
    return a;
}

// exact packed-int8x4 -> 2x half2: ((b^0x80)|0x6400) - 1152
__device__ __forceinline__ void cvt4_i8_f16(uint32_t v, uint32_t* h2) {
    const uint32_t u = v ^ 0x80808080u;
    uint32_t lo = __byte_perm(u, 0x64646464u, 0x4140);
    uint32_t hi = __byte_perm(u, 0x64646464u, 0x4342);
    const uint32_t bias_u = 0x64806480u;  // half2(1152, 1152)
    __half2 a = __hsub2(*reinterpret_cast<const __half2*>(&lo),
                        *reinterpret_cast<const __half2*>(&bias_u));
    __half2 c = __hsub2(*reinterpret_cast<const __half2*>(&hi),
                        *reinterpret_cast<const __half2*>(&bias_u));
    h2[0] = *reinterpret_cast<uint32_t*>(&a);
    h2[1] = *reinterpret_cast<uint32_t*>(&c);
}

// ---------------------------------------------------------------------------
__global__ void __launch_bounds__(256) prep_x(const float* __restrict__ x) {
    const size_t e = ((size_t)blockIdx.x * 256 + threadIdx.x) * 8;
    float4 f0 = *reinterpret_cast<const float4*>(x + e);
    float4 f1 = *reinterpret_cast<const float4*>(x + e + 4);
    __half2 h0 = __floats2half2_rn(f0.x, f0.y);
    __half2 h1 = __floats2half2_rn(f0.z, f0.w);
    __half2 h2 = __floats2half2_rn(f1.x, f1.y);
    __half2 h3 = __floats2half2_rn(f1.z, f1.w);
    uint4 st;
    st.x = *reinterpret_cast<uint32_t*>(&h0);
    st.y = *reinterpret_cast<uint32_t*>(&h1);
    st.z = *reinterpret_cast<uint32_t*>(&h2);
    st.w = *reinterpret_cast<uint32_t*>(&h3);
    *reinterpret_cast<uint4*>(g_xh + e) = st;
}

__global__ void __launch_bounds__(256) prep_w(const int* __restrict__ w) {
    const size_t e = ((size_t)blockIdx.x * 256 + threadIdx.x) * 8;
    int4 w0 = *reinterpret_cast<const int4*>(w + e);
    int4 w1 = *reinterpret_cast<const int4*>(w + e + 4);
    uint32_t t0 = __byte_perm((uint32_t)w0.x, (uint32_t)w0.y, 0x0040);
    uint32_t u0 = __byte_perm((uint32_t)w0.z, (uint32_t)w0.w, 0x0040);
    uint32_t r0 = __byte_perm(t0, u0, 0x5410);
    uint32_t t1 = __byte_perm((uint32_t)w1.x, (uint32_t)w1.y, 0x0040);
    uint32_t u1 = __byte_perm((uint32_t)w1.z, (uint32_t)w1.w, 0x0040);
    uint32_t r1 = __byte_perm(t1, u1, 0x5410);
    uint32_t h[4];
    cvt4_i8_f16(r0, h + 0);
    cvt4_i8_f16(r1, h + 2);
    *reinterpret_cast<uint4*>(g_wh + e) = make_uint4(h[0], h[1], h[2], h[3]);
}

// ---------------------------------------------------------------------------
__device__ __forceinline__ void cpa16(uint32_t dst, const void* src) {
    asm volatile("cp.async.cg.shared.global [%0], [%1], 16;"
                 :: "r"(dst), "l"(src) : "memory");
}
__device__ __forceinline__ void cp_commit() {
    asm volatile("cp.async.commit_group;" ::: "memory");
}
template <int N>
__device__ __forceinline__ void cp_wait() {
    asm volatile("cp.async.wait_group %0;" :: "n"(N) : "memory");
}
__device__ __forceinline__ void ldsm4(uint32_t* r, uint32_t addr) {
    asm volatile("ldmatrix.sync.aligned.m8n8.x4.shared.b16 {%0,%1,%2,%3}, [%4];"
                 : "=r"(r[0]), "=r"(r[1]), "=r"(r[2]), "=r"(r[3]) : "r"(addr));
}
__device__ __forceinline__ void mma16816(float* c, const uint32_t* a,
                                         uint32_t b0, uint32_t b1) {
    asm volatile(
        "mma.sync.aligned.m16n8k16.row.col.f32.f16.f16.f32 "
        "{%0,%1,%2,%3}, {%4,%5,%6,%7}, {%8,%9}, {%0,%1,%2,%3};"
        : "+f"(c[0]), "+f"(c[1]), "+f"(c[2]), "+f"(c[3])
        : "r"(a[0]), "r"(a[1]), "r"(a[2]), "r"(a[3]), "r"(b0), "r"(b1));
}

__global__ void __launch_bounds__(256, 1)
gemm_kernel(const float* __restrict__ scale, float* __restrict__ out) {
    extern __shared__ char smem[];
    const uint32_t raw   = smem_u32(smem);
    const uint32_t tiles = (raw + 1023u) & ~1023u;   // 1KB align for SW128

    const int tid  = threadIdx.x;
    const int lane = tid & 31;
    const int warp = tid >> 5;
    const int wm   = warp >> 2;   // 0..1  (64 m-rows each)
    const int wn   = warp & 3;    // 0..3  (64 n-cols each)

    // ---- grid swizzle: groups of GRP n-tiles x MT m-tiles ----
    const int lin    = blockIdx.x;            // 0 .. NT*MT-1
    const int grp    = lin / (GRP * MT);
    const int startn = grp * GRP;
    const int width  = (NT - startn < GRP) ? (NT - startn) : GRP;
    const int rem    = lin - grp * GRP * MT;
    const int n0     = (startn + rem % width) * BN;
    const int m0     = (rem / width) * BM;

    const __half* ag = g_xh + (size_t)m0 * GK;
    const __half* bg = g_wh + (size_t)n0 * GK;

    // A: 1024 16B-units (4/thread); W: 2048 units (8/thread)
    auto issue = [&](int kn) {
        const int s  = kn & (STAGES - 1);
        const int k0 = kn * BK;
        const uint32_t ab = tiles + s * STAGE_B;
        const uint32_t bb = ab + TILE_A;
#pragma unroll
        for (int p = 0; p < 4; ++p) {
            const int u = tid + p * 256;
            const int row = u >> 3, c = u & 7;
            const uint32_t o = SW128((uint32_t)(row * 128 + c * 16));
            cpa16(ab + o, ag + (size_t)row * GK + k0 + c * 8);
        }
#pragma unroll
        for (int p = 0; p < 8; ++p) {
            const int u = tid + p * 256;
            const int row = u >> 3, c = u & 7;
            const uint32_t o = SW128((uint32_t)(row * 128 + c * 16));
            cpa16(bb + o, bg + (size_t)row * GK + k0 + c * 8);
        }
        cp_commit();
    };

    issue(0); issue(1); issue(2);

    float acc[4][8][4];
#pragma unroll
    for (int t = 0; t < 4; ++t)
#pragma unroll
        for (int j = 0; j < 8; ++j)
#pragma unroll
            for (int e = 0; e < 4; ++e) acc[t][j][e] = 0.f;

    // ldmatrix per-lane address components (halves)
    const int row_a = wm * 64 + (lane & 15);                      // + t*16
    const int ka    = (lane >> 4) << 3;
    const int row_b = wn * 64 + ((lane >> 4) << 3) + (lane & 7);  // + g*16
    const int kb    = ((lane >> 3) & 1) << 3;

    for (int it = 0; it < KIT; ++it) {
        const int s = it & (STAGES - 1);

        cp_wait<2>();          // stage `it` complete (in-order groups)
        __syncthreads();       // visible CTA-wide; stage (it-1)&3 fully read

        if (it + 3 < KIT) issue(it + 3);
        else              cp_commit();   // keep group count invariant

        const uint32_t abase = tiles + s * STAGE_B;
        const uint32_t bbase = abase + TILE_A;

#pragma unroll
        for (int st = 0; st < 4; ++st) {           // 4 x k16 per BK=64
            const int k2 = st * 16;
            uint32_t a[4][4], b[4][4];
#pragma unroll
            for (int t = 0; t < 4; ++t) {
                const uint32_t o = (uint32_t)((row_a + t * 16) * 128 + (k2 + ka) * 2);
                ldsm4(a[t], abase + SW128(o));
            }
#pragma unroll
            for (int g = 0; g < 4; ++g) {
                const uint32_t o = (uint32_t)((row_b + g * 16) * 128 + (k2 + kb) * 2);
                ldsm4(b[g], bbase + SW128(o));
            }
#pragma unroll
            for (int t = 0; t < 4; ++t)
#pragma unroll
                for (int j = 0; j < 8; ++j) {
                    const int g = j >> 1, h = j & 1;
                    mma16816(acc[t][j], a[t], b[g][2 * h], b[g][2 * h + 1]);
                }
        }
        // no trailing barrier: next iteration's wait+barrier orders reuse
    }

    // ---- epilogue: scale, fp16 round (match reference), fp32 store ----
    const int mrow = m0 + wm * 64 + (lane >> 2);
    const int ncol = n0 + wn * 64 + (lane & 3) * 2;
    float* og = out + (size_t)mrow * GN + ncol;
    const float* scp = scale + ncol;

#pragma unroll
    for (int t = 0; t < 4; ++t) {
#pragma unroll
        for (int j = 0; j < 8; ++j) {
            const float2 sc = *reinterpret_cast<const float2*>(scp + j * 8);
            float2 r0, r1;
            r0.x = __half2float(__float2half_rn(acc[t][j][0] * sc.x));
            r0.y = __half2float(__float2half_rn(acc[t][j][1] * sc.y));
            r1.x = __half2float(__float2half_rn(acc[t][j][2] * sc.x));
            r1.y = __half2float(__float2half_rn(acc[t][j][3] * sc.y));
            *reinterpret_cast<float2*>(og + (size_t)(t * 16) * GN + j * 8)     = r0;
            *reinterpret_cast<float2*>(og + (size_t)(t * 16 + 8) * GN + j * 8) = r1;
        }
    }
}

}  // namespace

extern "C" void kernel_launch(void* const* d_in, const int* in_sizes, int n_in,
                              void* d_out, int out_size) {
    const float* x     = (const float*)d_in[0];
    const int*   w     = (const int*)d_in[1];
    const float* scale = (const float*)d_in[2];
    float*       out   = (float*)d_out;

    cudaFuncSetAttribute(gemm_kernel,
                         cudaFuncAttributeMaxDynamicSharedMemorySize, SMEM_BYTES);

    prep_x<<<GM * GK / 8 / 256, 256>>>(x);   // 16384 blocks
    prep_w<<<GN * GK / 8 / 256, 256>>>(w);   // 22016 blocks
    gemm_kernel<<<NT * MT, 256, SMEM_BYTES>>>(scale, out);
}

// round 11
// speedup vs baseline: 1.7243x; 1.1263x over previous
#include <cuda_runtime.h>
#include <cuda_fp16.h>
#include <stdint.h>

// ============================================================================
// Int8Linear — harness dtypes: x fp16->float32, w int8->int32, out fp16->float32.
//   out[m,n] = f32( fp16( fp32acc( x[m,:] . w[n,:] ) * scale[n] ) )
// M=8192, N=11008, K=4096.
// Round 11: 2 CTAs/SM for overhead hiding. CTA tile 128x128, warp tile 64x32,
// 3-stage cp.async.cg pipeline (96KB smem), SW128, flat ldsm->mma blocks,
// fused scale epilogue. Prep kernels compact operands to fp16 images.
// ============================================================================

namespace {

constexpr int GM = 8192;
constexpr int GN = 11008;
constexpr int GK = 4096;
constexpr int BM = 128;
constexpr int BN = 128;
constexpr int BK = 64;                    // 64 fp16 = 128B row (SW128 atom)
constexpr int KIT = GK / BK;              // 64
constexpr int NT = GN / BN;               // 86
constexpr int MT = GM / BM;               // 64
constexpr int STAGES = 3;
constexpr int TILE_B  = BM * 128;         // 16 KB
constexpr int STAGE_B = 2 * TILE_B;       // 32 KB
constexpr int SMEM_BYTES = 1024 + STAGES * STAGE_B;  // 99328 B (x2 < 228KB)

__device__ __align__(1024) __half g_xh[(size_t)GM * GK];   // 64 MB
__device__ __align__(1024) __half g_wh[(size_t)GN * GK];   // 90 MB

#define SW128(o) ((o) ^ (((o) >> 3) & 0x70u))

__device__ __forceinline__ uint32_t smem_u32(const void* p) {
    uint32_t a;
    asm("{ .reg .u64 t; cvta.to.shared.u64 t, %1; cvt.u32.u64 %0, t; }"
        : "=r"(a) : "l"(p));
    return a;
}

// exact packed-int8x4 -> 2x half2: ((b^0x80)|0x6400) - 1152
__device__ __forceinline__ void cvt4_i8_f16(uint32_t v, uint32_t* h2) {
    const uint32_t u = v ^ 0x80808080u;
    uint32_t lo = __byte_perm(u, 0x64646464u, 0x4140);
    uint32_t hi = __byte_perm(u, 0x64646464u, 0x4342);
    const uint32_t bias_u = 0x64806480u;  // half2(1152, 1152)
    __half2 a = __hsub2(*reinterpret_cast<const __half2*>(&lo),
                        *reinterpret_cast<const __half2*>(&bias_u));
    __half2 c = __hsub2(*reinterpret_cast<const __half2*>(&hi),
                        *reinterpret_cast<const __half2*>(&bias_u));
    h2[0] = *reinterpret_cast<uint32_t*>(&a);
    h2[1] = *reinterpret_cast<uint32_t*>(&c);
}

// ---------------------------------------------------------------------------
__global__ void __launch_bounds__(256) prep_x(const float* __restrict__ x) {
    const size_t e = ((size_t)blockIdx.x * 256 + threadIdx.x) * 8;
    float4 f0 = *reinterpret_cast<const float4*>(x + e);
    float4 f1 = *reinterpret_cast<const float4*>(x + e + 4);
    __half2 h0 = __floats2half2_rn(f0.x, f0.y);
    __half2 h1 = __floats2half2_rn(f0.z, f0.w);
    __half2 h2 = __floats2half2_rn(f1.x, f1.y);
    __half2 h3 = __floats2half2_rn(f1.z, f1.w);
    uint4 st;
    st.x = *reinterpret_cast<uint32_t*>(&h0);
    st.y = *reinterpret_cast<uint32_t*>(&h1);
    st.z = *reinterpret_cast<uint32_t*>(&h2);
    st.w = *reinterpret_cast<uint32_t*>(&h3);
    *reinterpret_cast<uint4*>(g_xh + e) = st;
}

__global__ void __launch_bounds__(256) prep_w(const int* __restrict__ w) {
    const size_t e = ((size_t)blockIdx.x * 256 + threadIdx.x) * 8;
    int4 w0 = *reinterpret_cast<const int4*>(w + e);
    int4 w1 = *reinterpret_cast<const int4*>(w + e + 4);
    uint32_t t0 = __byte_perm((uint32_t)w0.x, (uint32_t)w0.y, 0x0040);
    uint32_t u0 = __byte_perm((uint32_t)w0.z, (uint32_t)w0.w, 0x0040);
    uint32_t r0 = __byte_perm(t0, u0, 0x5410);
    uint32_t t1 = __byte_perm((uint32_t)w1.x, (uint32_t)w1.y, 0x0040);
    uint32_t u1 = __byte_perm((uint32_t)w1.z, (uint32_t)w1.w, 0x0040);
    uint32_t r1 = __byte_perm(t1, u1, 0x5410);
    uint32_t h[4];
    cvt4_i8_f16(r0, h + 0);
    cvt4_i8_f16(r1, h + 2);
    *reinterpret_cast<uint4*>(g_wh + e) = make_uint4(h[0], h[1], h[2], h[3]);
}

// ---------------------------------------------------------------------------
__device__ __forceinline__ void cpa16(uint32_t dst, const void* src) {
    asm volatile("cp.async.cg.shared.global [%0], [%1], 16;"
                 :: "r"(dst), "l"(src) : "memory");
}
__device__ __forceinline__ void cp_commit() {
    asm volatile("cp.async.commit_group;" ::: "memory");
}
template <int N>
__device__ __forceinline__ void cp_wait() {
    asm volatile("cp.async.wait_group %0;" :: "n"(N) : "memory");
}
__device__ __forceinline__ void ldsm4(uint32_t* r, uint32_t addr) {
    asm volatile("ldmatrix.sync.aligned.m8n8.x4.shared.b16 {%0,%1,%2,%3}, [%4];"
                 : "=r"(r[0]), "=r"(r[1]), "=r"(r[2]), "=r"(r[3]) : "r"(addr));
}
__device__ __forceinline__ void mma16816(float* c, const uint32_t* a,
                                         uint32_t b0, uint32_t b1) {
    asm volatile(
        "mma.sync.aligned.m16n8k16.row.col.f32.f16.f16.f32 "
        "{%0,%1,%2,%3}, {%4,%5,%6,%7}, {%8,%9}, {%0,%1,%2,%3};"
        : "+f"(c[0]), "+f"(c[1]), "+f"(c[2]), "+f"(c[3])
        : "r"(a[0]), "r"(a[1]), "r"(a[2]), "r"(a[3]), "r"(b0), "r"(b1));
}

__global__ void __launch_bounds__(256, 2)
gemm_kernel(const float* __restrict__ scale, float* __restrict__ out) {
    extern __shared__ char smem[];
    const uint32_t raw   = smem_u32(smem);
    const uint32_t tiles = (raw + 1023u) & ~1023u;   // 1KB align for SW128

    const int tid  = threadIdx.x;
    const int lane = tid & 31;
    const int warp = tid >> 5;
    const int wm   = warp >> 2;   // 0..1  (64 m-rows each)
    const int wn   = warp & 3;    // 0..3  (32 n-cols each)
    const int n0   = blockIdx.x * BN;   // N fastest -> W image L2-resident
    const int m0   = blockIdx.y * BM;

    const __half* ag = g_xh + (size_t)m0 * GK;
    const __half* bg = g_wh + (size_t)n0 * GK;

    // A and W: 1024 16B-units each -> 4 cpa16/thread each
    auto issue = [&](int kn) {
        const int s  = kn % STAGES;
        const int k0 = kn * BK;
        const uint32_t ab = tiles + s * STAGE_B;
        const uint32_t bb = ab + TILE_B;
#pragma unroll
        for (int p = 0; p < 4; ++p) {
            const int u = tid + p * 256;
            const int row = u >> 3, c = u & 7;
            const uint32_t o = SW128((uint32_t)(row * 128 + c * 16));
            cpa16(ab + o, ag + (size_t)row * GK + k0 + c * 8);
        }
#pragma unroll
        for (int p = 0; p < 4; ++p) {
            const int u = tid + p * 256;
            const int row = u >> 3, c = u & 7;
            const uint32_t o = SW128((uint32_t)(row * 128 + c * 16));
            cpa16(bb + o, bg + (size_t)row * GK + k0 + c * 8);
        }
        cp_commit();
    };

    issue(0); issue(1);

    float acc[4][4][4];
#pragma unroll
    for (int t = 0; t < 4; ++t)
#pragma unroll
        for (int j = 0; j < 4; ++j)
#pragma unroll
            for (int e = 0; e < 4; ++e) acc[t][j][e] = 0.f;

    // ldmatrix per-lane address components (halves)
    const int row_a = wm * 64 + (lane & 15);                      // + t*16
    const int ka    = (lane >> 4) << 3;
    const int row_b = wn * 32 + ((lane >> 4) << 3) + (lane & 7);  // + g*16
    const int kb    = ((lane >> 3) & 1) << 3;

    for (int it = 0; it < KIT; ++it) {
        const int s = it % STAGES;

        cp_wait<1>();          // stage `it` complete (one group outstanding)
        __syncthreads();       // visible CTA-wide; previous stage fully read

        if (it + 2 < KIT) issue(it + 2);
        else              cp_commit();   // keep group count invariant

        const uint32_t abase = tiles + s * STAGE_B;
        const uint32_t bbase = abase + TILE_B;

#pragma unroll
        for (int st = 0; st < 4; ++st) {           // 4 x k16 per BK=64
            const int k2 = st * 16;
            uint32_t a[4][4], b[2][4];
#pragma unroll
            for (int t = 0; t < 4; ++t) {
                const uint32_t o = (uint32_t)((row_a + t * 16) * 128 + (k2 + ka) * 2);
                ldsm4(a[t], abase + SW128(o));
            }
#pragma unroll
            for (int g = 0; g < 2; ++g) {
                const uint32_t o = (uint32_t)((row_b + g * 16) * 128 + (k2 + kb) * 2);
                ldsm4(b[g], bbase + SW128(o));
            }
#pragma unroll
            for (int t = 0; t < 4; ++t)
#pragma unroll
                for (int j = 0; j < 4; ++j) {
                    const int g = j >> 1, h = j & 1;
                    mma16816(acc[t][j], a[t], b[g][2 * h], b[g][2 * h + 1]);
                }
        }
        // no trailing barrier: next iteration's wait+barrier orders reuse
    }

    // ---- epilogue: scale, fp16 round (match reference), fp32 store ----
    const int mrow = m0 + wm * 64 + (lane >> 2);
    const int ncol = n0 + wn * 32 + (lane & 3) * 2;
    float* og = out + (size_t)mrow * GN + ncol;
    const float* scp = scale + ncol;

#pragma unroll
    for (int t = 0; t < 4; ++t) {
#pragma unroll
        for (int j = 0; j < 4; ++j) {
            const float2 sc = *reinterpret_cast<const float2*>(scp + j * 8);
            float2 r0, r1;
            r0.x = __half2float(__float2half_rn(acc[t][j][0] * sc.x));
            r0.y = __half2float(__float2half_rn(acc[t][j][1] * sc.y));
            r1.x = __half2float(__float2half_rn(acc[t][j][2] * sc.x));
            r1.y = __half2float(__float2half_rn(acc[t][j][3] * sc.y));
            *reinterpret_cast<float2*>(og + (size_t)(t * 16) * GN + j * 8)     = r0;
            *reinterpret_cast<float2*>(og + (size_t)(t * 16 + 8) * GN + j * 8) = r1;
        }
    }
}

}  // namespace

extern "C" void kernel_launch(void* const* d_in, const int* in_sizes, int n_in,
                              void* d_out, int out_size) {
    const float* x     = (const float*)d_in[0];
    const int*   w     = (const int*)d_in[1];
    const float* scale = (const float*)d_in[2];
    float*       out   = (float*)d_out;

    cudaFuncSetAttribute(gemm_kernel,
                         cudaFuncAttributeMaxDynamicSharedMemorySize, SMEM_BYTES);

    prep_x<<<GM * GK / 8 / 256, 256>>>(x);   // 16384 blocks
    prep_w<<<GN * GK / 8 / 256, 256>>>(w);   // 22016 blocks
    gemm_kernel<<<dim3(NT, MT), 256, SMEM_BYTES>>>(scale, out);
}